// round 8
// baseline (speedup 1.0000x reference)
#include <cuda_runtime.h>
#include <cuda_fp16.h>

// B=8192, T=16, M=16, V=256 fixed.
#define INS_DEL 10.0f
#define FIRST_CHAR_COST 10.0f

#define WARPS_PER_BLOCK 4
#define THREADS_PER_BLOCK (WARPS_PER_BLOCK * 32)

#define K10 4.5399929762484854e-05f          // e^{-10}

// Per-warp E: 16 rows x 256 halves (512B row), XOR-swizzled 16B granules:
// granule' = granule ^ (row & 7). STS conflict-free (permutation), ldmatrix
// conflict-free (8 rows -> 8 distinct granule groups).
#define E_HALVES (16 * 256)                  // 8192 B / warp
#define SSTRIDE 18
#define S_FLOATS 292                         // 288 + pad

__device__ __forceinline__ void ldsm_x4(unsigned &r0, unsigned &r1,
                                        unsigned &r2, unsigned &r3,
                                        unsigned saddr) {
    asm volatile("ldmatrix.sync.aligned.m8n8.x4.shared.b16 {%0,%1,%2,%3}, [%4];\n"
                 : "=r"(r0), "=r"(r1), "=r"(r2), "=r"(r3) : "r"(saddr));
}

__device__ __forceinline__ void mma16816(float d[4],
                                         unsigned a0, unsigned a1,
                                         unsigned a2, unsigned a3,
                                         unsigned b0, unsigned b1) {
    asm volatile("mma.sync.aligned.m16n8k16.row.col.f32.f16.f16.f32 "
                 "{%0,%1,%2,%3}, {%4,%5,%6,%7}, {%8,%9}, {%0,%1,%2,%3};\n"
                 : "+f"(d[0]), "+f"(d[1]), "+f"(d[2]), "+f"(d[3])
                 : "r"(a0), "r"(a1), "r"(a2), "r"(a3), "r"(b0), "r"(b1));
}

__device__ __forceinline__ unsigned pack_h2(float x, float y) {
    __half2 h = __floats2half2_rn(x, y);
    return *(unsigned*)&h;
}

__global__ void __launch_bounds__(THREADS_PER_BLOCK, 6)
rhyme_dp_kernel(const float* __restrict__ logits,
                const int* __restrict__ tgt,
                const float* __restrict__ phon,
                float* __restrict__ out, int B)
{
    __shared__ __half sE[WARPS_PER_BLOCK][E_HALVES];
    __shared__ float  sS[WARPS_PER_BLOCK][S_FLOATS];

    const int w    = threadIdx.x >> 5;
    const int lane = threadIdx.x & 31;
    const int b    = blockIdx.x * WARPS_PER_BLOCK + w;

    __half* E = sE[w];
    float*  S = sS[w];

    const float* lg = logits + (size_t)b * (16 * 256);
    const int m = lane & 15;

    const int gm = tgt[b * 16 + m];
    const int g0 = __shfl_sync(0xffffffffu, gm, 0);

    // -------- Phase 1: raw exp -> shared E (half, swizzled). ----------------
    {
        const float4* rows = (const float4*)lg;   // 16 rows x 64 float4
        const int li = lane * 2;
#pragma unroll
        for (int t = 0; t < 16; ++t) {
            float4 x0 = rows[t * 64 + li];
            float4 x1 = rows[t * 64 + li + 1];
            unsigned h[4];
            h[0] = pack_h2(__expf(x0.x), __expf(x0.y));
            h[1] = pack_h2(__expf(x0.z), __expf(x0.w));
            h[2] = pack_h2(__expf(x1.x), __expf(x1.y));
            h[3] = pack_h2(__expf(x1.z), __expf(x1.w));
            const int gr = lane ^ (t & 7);                  // swizzled granule
            *(uint4*)(E + t * 256 + gr * 8) = *(uint4*)h;
        }
    }
    __syncwarp();

    // -------- Phase 2: [sub_raw | Z] = E @ [C_gather | ones] via HMMA -------
    float d0[4] = {0.f, 0.f, 0.f, 0.f};
    float d1[4] = {0.f, 0.f, 0.f, 0.f};
    float d2[4] = {0.f, 0.f, 0.f, 0.f};
    float z0_lane0;
    {
        const unsigned ebase = (unsigned)__cvta_generic_to_shared(E);
        const unsigned r   = lane & 15;       // ldmatrix row
        const unsigned rx  = r & 7;           // swizzle key
        const unsigned hi  = lane >> 4;       // 16B half-column select
        const unsigned rowoff = ebase + r * 512;

        const int gn0 = __shfl_sync(0xffffffffu, gm, lane >> 2);
        const int gn1 = __shfl_sync(0xffffffffu, gm, 8 + (lane >> 2));
        const float* r0 = phon + (size_t)gn0 * 256 + (lane & 3) * 2;
        const float* r1 = phon + (size_t)gn1 * 256 + (lane & 3) * 2;

        const unsigned bone = (lane < 4) ? pack_h2(1.0f, 1.0f) : 0u;

#pragma unroll
        for (int kt = 0; kt < 16; ++kt) {
            unsigned a0, a1, a2, a3;
            const unsigned g = (unsigned)(kt * 2) + hi;
            ldsm_x4(a0, a1, a2, a3, rowoff + ((g ^ rx) << 4));

            float2 f00 = __ldg((const float2*)(r0 + kt * 16));
            float2 f01 = __ldg((const float2*)(r0 + kt * 16 + 8));
            float2 f10 = __ldg((const float2*)(r1 + kt * 16));
            float2 f11 = __ldg((const float2*)(r1 + kt * 16 + 8));

            mma16816(d0, a0, a1, a2, a3,
                     pack_h2(f00.x, f00.y), pack_h2(f01.x, f01.y));
            mma16816(d1, a0, a1, a2, a3,
                     pack_h2(f10.x, f10.y), pack_h2(f11.x, f11.y));
            mma16816(d2, a0, a1, a2, a3, bone, bone);
        }

        // -------- writeback: S[t][m] = exp(-sub[t][m]) ----------------------
        const float zlo = __shfl_sync(0xffffffffu, d2[0], lane & ~3);
        const float zhi = __shfl_sync(0xffffffffu, d2[2], lane & ~3);
        z0_lane0 = __shfl_sync(0xffffffffu, d2[0], 0);   // Z[0]
        const float rzlo = -__fdividef(1.0f, zlo);
        const float rzhi = -__fdividef(1.0f, zhi);

        const int tq = lane >> 2;
        const int mc = (lane & 3) * 2;
        *(float2*)(S + tq * SSTRIDE + mc) =
            make_float2(__expf(d0[0] * rzlo), __expf(d0[1] * rzlo));
        *(float2*)(S + (tq + 8) * SSTRIDE + mc) =
            make_float2(__expf(d0[2] * rzhi), __expf(d0[3] * rzhi));
        *(float2*)(S + tq * SSTRIDE + mc + 8) =
            make_float2(__expf(d1[0] * rzlo), __expf(d1[1] * rzlo));
        *(float2*)(S + (tq + 8) * SSTRIDE + mc + 8) =
            make_float2(__expf(d1[2] * rzhi), __expf(d1[3] * rzhi));
    }
    __syncwarp();

    // -------- Phase 3: soft-DP wavefront in w-domain (w = exp(-dp)) ---------
    // w(i,j) = e^-10 * (w_up + w_left) + w_diag * exp(-sub[i-1][j-1])
    const float em1 = __expf(-10.0f * (float)(m + 1));   // w(0, m+1)
    const float em  = __expf(-10.0f * (float)m);         // w(0, m)
    float bl = K10;    // lane-0 running e^{-10*i}
    float bd = 1.0f;   // lane-0 running e^{-10*(i-1)}

    float cur = 0.0f, prev = 0.0f;
#pragma unroll
    for (int s = 0; s <= 30; ++s) {
        float leftv = __shfl_up_sync(0xffffffffu, cur, 1);
        float diagv = __shfl_up_sync(0xffffffffu, prev, 1);
        const int i = s - m + 1;
        const bool active = (i >= 1) && (i <= 16);

        float up = cur;
        if (i == 1) { up = em1; diagv = em; }
        if (m == 0) { leftv = bl; diagv = bd; }

        const int si = active ? (s - m) : 0;
        const float es = S[si * SSTRIDE + m];

        const float val = K10 * (up + leftv) + diagv * es;

        if (active) { prev = cur; cur = val; }
        bd = bl; bl *= K10;
    }

    // -------- Phase 4: final log + first-char term + output -----------------
    if (lane == 15) {
        // E row 0 swizzle: element g0 -> granule (g0>>3) ^ 0, unchanged.
        const float fm = __half2float(E[g0]) * __fdividef(1.0f, z0_lane0);
        out[b] = -__logf(cur) + FIRST_CHAR_COST * (1.0f - fm);
    }
}

extern "C" void kernel_launch(void* const* d_in, const int* in_sizes, int n_in,
                              void* d_out, int out_size)
{
    const float* logits = (const float*)d_in[0];   // tail_logits (B,T,V) f32
    const int*   tgt    = (const int*)  d_in[1];   // target_idx  (B,M) i32
    const float* phon   = (const float*)d_in[2];   // phon_cost   (V,V) f32
    float* out = (float*)d_out;
    const int B = out_size;                        // 8192

    const int grid = (B + WARPS_PER_BLOCK - 1) / WARPS_PER_BLOCK;
    rhyme_dp_kernel<<<grid, THREADS_PER_BLOCK>>>(logits, tgt, phon, out, B);
}